// round 11
// baseline (speedup 1.0000x reference)
#include <cuda_runtime.h>
#include <cstdint>

// SSDIntNBitTableBatchedEmbeddingBags: T=2 tables [ROWS=1M, D=128] of uint8
// codes promoted by the harness to INT32 (confirmed R6), per-row scale/bias,
// bag L=50, B=4096, output [B, T*D] f32.
//
// R11 = R10 with the WAR race FIXED.
//   R10 bug: iteration l issued the prefetch for row l+8 into slot
//   (l+8)&7 == l&7 BEFORE reading slot l&7; wait_group(7) retires only the
//   OLDEST groups, so the new in-flight copy could overwrite the slot before
//   the LDS whenever the row hit L2/L1 (fast return) -> ~3% corruption.
//   Fix: read-then-issue. Per iteration: wait_group(STAGE-1) certifies row
//   l's group retired; LDS the slot; only then issue row l+8 into that slot
//   and commit. The overwrite is after the read in program order and its
//   store phase lands >=hundreds of cycles later -> no hazard.
//
// Design rationale (R8 evidence): regs=40 showed ptxas collapsed a register
// ring to ~4-deep; DRAM idle 38% of cycles => latency-starved. cp.async's
// destination is SMEM: depth-8 costs no registers and cannot be flattened.
// 8 warps x 8 slots x 512B = 32KB static smem/block. .cg keeps the one-pass
// qweight stream out of L1. Each lane reads back only its own copied 16B
// (own-thread LDGSTS->LDS ordering via wait_group; no syncwarp).
//
// Input binding is evidence-based (order-agnostic): qweights = unique max;
// scales/biases = equal-sized pair split by sign ballot; indices = leftover.
// qweights dtype (i32 promoted vs packed u8) re-checked by ballot each run.

static constexpr int T_TABLES = 2;
static constexpr int BAG_L    = 50;
static constexpr int DIM      = 128;   // elements per row
static constexpr int STAGE    = 8;     // cp.async ring depth (power of two)
static constexpr int WARPS    = 8;     // warps per block

__device__ __forceinline__ int bag_row(int i0, int i1, int l)
{
    return (l < 32) ? __shfl_sync(0xffffffffu, i0, l)
                    : __shfl_sync(0xffffffffu, i1, l - 32);
}

__device__ __forceinline__ void cp_async_16(uint32_t smem_addr, const void* gptr)
{
    asm volatile("cp.async.cg.shared.global [%0], [%1], 16;\n"
                 :: "r"(smem_addr), "l"(gptr));
}
__device__ __forceinline__ void cp_async_commit()
{
    asm volatile("cp.async.commit_group;\n" ::: "memory");
}
__device__ __forceinline__ void cp_async_wait_all_but()
{
    asm volatile("cp.async.wait_group %0;\n" :: "n"(STAGE - 1) : "memory");
}

__global__ __launch_bounds__(WARPS * 32)
void emb_bag_kernel(const void*  __restrict__ qw,
                    const float* __restrict__ candA,
                    const float* __restrict__ candB,
                    const int*   __restrict__ indices,
                    float*       __restrict__ out,
                    int B, int n_rows)
{
    // ring: [warp][slot][lane] 16B each  -> 8*8*32*16 = 32 KB
    __shared__ int4 ring[WARPS][STAGE][32];

    const int lane = threadIdx.x & 31;
    const int wid  = (threadIdx.x >> 5);

    // ---- inline input classification (per-warp, L1-broadcast loads) ----
    const unsigned negA =
        __ballot_sync(0xffffffffu, candA[lane] < 0.0f);
    const float* __restrict__ scales = negA ? candB : candA;
    const float* __restrict__ biases = negA ? candA : candB;

    const unsigned widebits =
        __ballot_sync(0xffffffffu,
            (reinterpret_cast<const uint32_t*>(qw)[lane] & 0xFFFFFF00u) != 0u);
    const bool qw_is_i32 = (widebits == 0u);

    const int warp_global = (blockIdx.x * blockDim.x + threadIdx.x) >> 5;
    const int n_bags = T_TABLES * B;
    if (warp_global >= n_bags) return;

    const int t = warp_global / B;
    const int b = warp_global - t * B;

    // ---- preload bag's 50 indices + per-row scale/bias across lanes ----
    const int* __restrict__ idx = indices + (size_t)warp_global * BAG_L;
    const float* __restrict__ sc = scales + (size_t)t * n_rows;
    const float* __restrict__ bs = biases + (size_t)t * n_rows;

    const int i0 = idx[lane];                                   // l = 0..31
    const int l1 = (32 + lane < BAG_L) ? 32 + lane : BAG_L - 1; // clamp
    const int i1 = idx[l1];                                     // l = 32..49

    const float s0 = sc[i0], s1 = sc[i1];
    const float a0 = bs[i0], a1 = bs[i1];

    float acc0 = 0.f, acc1 = 0.f, acc2 = 0.f, acc3 = 0.f;
    float accb = 0.f;   // dim-invariant bias sum

    if (qw_is_i32) {
        // int32 codes: row = 128 x i32 = 512 B; lane d owns int4 at elem 4d.
        const int4* __restrict__ base =
            reinterpret_cast<const int4*>(qw)
            + (size_t)t * n_rows * (DIM / 4) + lane;

        // ---- prologue: fill the ring, one commit group per row ----
#pragma unroll
        for (int p = 0; p < STAGE; ++p) {
            const int row = bag_row(i0, i1, p);
            cp_async_16((uint32_t)__cvta_generic_to_shared(&ring[wid][p][lane]),
                        &base[(size_t)row * (DIM / 4)]);
            cp_async_commit();
        }

        // ---- steady state: WAIT -> READ -> ISSUE -> COMMIT -------------
        // At iter l: after wait_group(STAGE-1), pending <= STAGE-1, so row
        // l's group (the (l+1)-oldest) has retired -> slot l&7 is valid.
        // The refill of slot l&7 (row l+8) is issued only AFTER the LDS.
#pragma unroll
        for (int l = 0; l < BAG_L; ++l) {
            cp_async_wait_all_but();

            const int4 q = ring[wid][l & (STAGE - 1)][lane];

            if (l + STAGE < BAG_L) {
                const int row = bag_row(i0, i1, l + STAGE);
                cp_async_16((uint32_t)__cvta_generic_to_shared(
                                &ring[wid][l & (STAGE - 1)][lane]),
                            &base[(size_t)row * (DIM / 4)]);
            }
            cp_async_commit();          // real or empty group (tail)

            float s, bb;
            if (l < 32) {
                s  = __shfl_sync(0xffffffffu, s0, l);
                bb = __shfl_sync(0xffffffffu, a0, l);
            } else {
                s  = __shfl_sync(0xffffffffu, s1, l - 32);
                bb = __shfl_sync(0xffffffffu, a1, l - 32);
            }
            acc0 = fmaf((float)q.x, s, acc0);
            acc1 = fmaf((float)q.y, s, acc1);
            acc2 = fmaf((float)q.z, s, acc2);
            acc3 = fmaf((float)q.w, s, acc3);
            accb += bb;
        }
    } else {
        // packed uint8 fallback: row = 128 B; lane d -> bytes [4d, 4d+4).
        const uint8_t* __restrict__ base8 =
            reinterpret_cast<const uint8_t*>(qw)
            + (size_t)t * n_rows * DIM + (size_t)lane * 4;

#pragma unroll
        for (int l = 0; l < BAG_L; ++l) {
            const int row = bag_row(i0, i1, l);
            float s, bb;
            if (l < 32) {
                s  = __shfl_sync(0xffffffffu, s0, l);
                bb = __shfl_sync(0xffffffffu, a0, l);
            } else {
                s  = __shfl_sync(0xffffffffu, s1, l - 32);
                bb = __shfl_sync(0xffffffffu, a1, l - 32);
            }
            const uint32_t q =
                *reinterpret_cast<const uint32_t*>(base8 + (size_t)row * DIM);
            acc0 = fmaf((float)( q         & 0xFFu), s, acc0);
            acc1 = fmaf((float)((q >> 8 )  & 0xFFu), s, acc1);
            acc2 = fmaf((float)((q >> 16)  & 0xFFu), s, acc2);
            acc3 = fmaf((float)( q >> 24          ), s, acc3);
            accb += bb;
        }
    }

    // out[b, t*DIM + 4*lane .. +3] — coalesced float4 store
    float4 r = make_float4(acc0 + accb, acc1 + accb, acc2 + accb, acc3 + accb);
    float* o = out + (size_t)b * (T_TABLES * DIM) + (size_t)t * DIM + lane * 4;
    *reinterpret_cast<float4*>(o) = r;
}

extern "C" void kernel_launch(void* const* d_in, const int* in_sizes, int n_in,
                              void* d_out, int out_size)
{
    // classify inputs by element count (order-agnostic):
    // qweights = unique max; scales/biases = the equal-sized pair; indices = rest
    int qi = 0;
    for (int i = 1; i < n_in; ++i)
        if (in_sizes[i] > in_sizes[qi]) qi = i;

    int c0 = -1, c1 = -1;
    for (int i = 0; i < n_in && c0 < 0; ++i) {
        if (i == qi) continue;
        for (int j = i + 1; j < n_in; ++j) {
            if (j == qi) continue;
            if (in_sizes[i] == in_sizes[j]) { c0 = i; c1 = j; break; }
        }
    }
    int ii = -1;
    for (int i = 0; i < n_in; ++i)
        if (i != qi && i != c0 && i != c1) ii = i;

    const void*  qw      = d_in[qi];
    const float* candA   = (const float*)d_in[c0];
    const float* candB   = (const float*)d_in[c1];
    const int*   indices = (const int*)  d_in[ii];
    float*       out     = (float*)      d_out;

    const int B      = in_sizes[ii] / (T_TABLES * BAG_L);
    const int n_rows = in_sizes[c0] / T_TABLES;

    const int n_bags  = T_TABLES * B;            // 8192 warps
    const int threads = WARPS * 32;
    const int blocks  = (n_bags + WARPS - 1) / WARPS;

    emb_bag_kernel<<<blocks, threads>>>(qw, candA, candB, indices, out,
                                        B, n_rows);
}

// round 12
// speedup vs baseline: 1.1478x; 1.1478x over previous
#include <cuda_runtime.h>
#include <cstdint>

// SSDIntNBitTableBatchedEmbeddingBags: T=2 tables [ROWS=1M, D=128] of uint8
// codes promoted by the harness to INT32 (confirmed R6), per-row scale/bias,
// bag L=50, B=4096, output [B, T*D] f32.
//
// R12 = R8 core (register ring, best: 43.0us) + fine-grained scheduling.
//   R11 falsified the per-warp-MLP theory: guaranteed depth-8 cp.async gave
//   DRAM 57.6% vs R8's 61.5% (and was slower). Aggregate concurrency already
//   covers latency; the residual DRAM idle is wave raggedness (1024 blocks,
//   6-block/SM cap -> ragged 136-block tail wave) + cross-CTA L1tex-queue
//   completion spread. Fix: 64-thread blocks (2 warps = 2 bags), 4096 blocks
//   -> ~25 co-resident blocks/SM, block-granularity back-fill, tail cost
//   drops from ~1/7 of runtime to ~1/28.
//
// Gather: one warp per (t,b) bag; lane d owns row elements [4d,4d+4) as one
// int4 -> warp = one coalesced 512B request per gathered row; __ldcs keeps
// the one-pass stream from thrashing L2 (scales/biases stay L2-resident).
// Bag's 50 indices/scales/biases preloaded across lanes, shfl-broadcast in a
// fully unrolled loop. Bias is dim-invariant: one scalar accumulator.
//
// Input binding is evidence-based (order-agnostic): qweights = unique max;
// scales/biases = equal-sized pair split by sign ballot; indices = leftover.
// qweights dtype (i32 promoted vs packed u8) re-checked by ballot each run.

static constexpr int T_TABLES = 2;
static constexpr int BAG_L    = 50;
static constexpr int DIM      = 128;   // elements per row
static constexpr int PIPE     = 8;     // prefetch ring (ptxas keeps ~4 live)
static constexpr int WARPS    = 2;     // warps per block (fine-grained)

__device__ __forceinline__ int bag_row(int i0, int i1, int l)
{
    return (l < 32) ? __shfl_sync(0xffffffffu, i0, l)
                    : __shfl_sync(0xffffffffu, i1, l - 32);
}

__global__ __launch_bounds__(WARPS * 32)
void emb_bag_kernel(const void*  __restrict__ qw,
                    const float* __restrict__ candA,
                    const float* __restrict__ candB,
                    const int*   __restrict__ indices,
                    float*       __restrict__ out,
                    int B, int n_rows)
{
    const int lane = threadIdx.x & 31;

    // ---- inline input classification (per-warp, L1-broadcast loads) ----
    const unsigned negA =
        __ballot_sync(0xffffffffu, candA[lane] < 0.0f);
    const float* __restrict__ scales = negA ? candB : candA;
    const float* __restrict__ biases = negA ? candA : candB;

    const unsigned widebits =
        __ballot_sync(0xffffffffu,
            (reinterpret_cast<const uint32_t*>(qw)[lane] & 0xFFFFFF00u) != 0u);
    const bool qw_is_i32 = (widebits == 0u);

    const int warp_global = (blockIdx.x * blockDim.x + threadIdx.x) >> 5;
    const int n_bags = T_TABLES * B;
    if (warp_global >= n_bags) return;

    const int t = warp_global / B;
    const int b = warp_global - t * B;

    // ---- preload bag's 50 indices + per-row scale/bias across lanes ----
    const int* __restrict__ idx = indices + (size_t)warp_global * BAG_L;
    const float* __restrict__ sc = scales + (size_t)t * n_rows;
    const float* __restrict__ bs = biases + (size_t)t * n_rows;

    const int i0 = idx[lane];                                   // l = 0..31
    const int l1 = (32 + lane < BAG_L) ? 32 + lane : BAG_L - 1; // clamp
    const int i1 = idx[l1];                                     // l = 32..49

    const float s0 = sc[i0], s1 = sc[i1];
    const float a0 = bs[i0], a1 = bs[i1];

    float acc0 = 0.f, acc1 = 0.f, acc2 = 0.f, acc3 = 0.f;
    float accb = 0.f;   // dim-invariant bias sum

    if (qw_is_i32) {
        // int32 codes: row = 128 x i32 = 512 B; lane d -> int4 at elem 4d.
        const int4* __restrict__ base =
            reinterpret_cast<const int4*>(qw)
            + (size_t)t * n_rows * (DIM / 4) + lane;

        // ---- register prefetch ring (R8-proven) ----
        int4 buf[PIPE];
#pragma unroll
        for (int p = 0; p < PIPE; ++p)
            buf[p] = __ldcs(&base[(size_t)bag_row(i0, i1, p) * (DIM / 4)]);

#pragma unroll
        for (int l = 0; l < BAG_L; ++l) {
            const int4 q = buf[l & (PIPE - 1)];
            if (l + PIPE < BAG_L)
                buf[l & (PIPE - 1)] =
                    __ldcs(&base[(size_t)bag_row(i0, i1, l + PIPE) * (DIM / 4)]);

            float s, bb;
            if (l < 32) {
                s  = __shfl_sync(0xffffffffu, s0, l);
                bb = __shfl_sync(0xffffffffu, a0, l);
            } else {
                s  = __shfl_sync(0xffffffffu, s1, l - 32);
                bb = __shfl_sync(0xffffffffu, a1, l - 32);
            }
            acc0 = fmaf((float)q.x, s, acc0);
            acc1 = fmaf((float)q.y, s, acc1);
            acc2 = fmaf((float)q.z, s, acc2);
            acc3 = fmaf((float)q.w, s, acc3);
            accb += bb;
        }
    } else {
        // packed uint8 fallback: row = 128 B; lane d -> bytes [4d, 4d+4).
        const uint8_t* __restrict__ base8 =
            reinterpret_cast<const uint8_t*>(qw)
            + (size_t)t * n_rows * DIM + (size_t)lane * 4;

#pragma unroll
        for (int l = 0; l < BAG_L; ++l) {
            const int row = bag_row(i0, i1, l);
            float s, bb;
            if (l < 32) {
                s  = __shfl_sync(0xffffffffu, s0, l);
                bb = __shfl_sync(0xffffffffu, a0, l);
            } else {
                s  = __shfl_sync(0xffffffffu, s1, l - 32);
                bb = __shfl_sync(0xffffffffu, a1, l - 32);
            }
            const uint32_t q =
                *reinterpret_cast<const uint32_t*>(base8 + (size_t)row * DIM);
            acc0 = fmaf((float)( q         & 0xFFu), s, acc0);
            acc1 = fmaf((float)((q >> 8 )  & 0xFFu), s, acc1);
            acc2 = fmaf((float)((q >> 16)  & 0xFFu), s, acc2);
            acc3 = fmaf((float)( q >> 24          ), s, acc3);
            accb += bb;
        }
    }

    // out[b, t*DIM + 4*lane .. +3] — coalesced float4 store
    float4 r = make_float4(acc0 + accb, acc1 + accb, acc2 + accb, acc3 + accb);
    float* o = out + (size_t)b * (T_TABLES * DIM) + (size_t)t * DIM + lane * 4;
    *reinterpret_cast<float4*>(o) = r;
}

extern "C" void kernel_launch(void* const* d_in, const int* in_sizes, int n_in,
                              void* d_out, int out_size)
{
    // classify inputs by element count (order-agnostic):
    // qweights = unique max; scales/biases = the equal-sized pair; indices = rest
    int qi = 0;
    for (int i = 1; i < n_in; ++i)
        if (in_sizes[i] > in_sizes[qi]) qi = i;

    int c0 = -1, c1 = -1;
    for (int i = 0; i < n_in && c0 < 0; ++i) {
        if (i == qi) continue;
        for (int j = i + 1; j < n_in; ++j) {
            if (j == qi) continue;
            if (in_sizes[i] == in_sizes[j]) { c0 = i; c1 = j; break; }
        }
    }
    int ii = -1;
    for (int i = 0; i < n_in; ++i)
        if (i != qi && i != c0 && i != c1) ii = i;

    const void*  qw      = d_in[qi];
    const float* candA   = (const float*)d_in[c0];
    const float* candB   = (const float*)d_in[c1];
    const int*   indices = (const int*)  d_in[ii];
    float*       out     = (float*)      d_out;

    const int B      = in_sizes[ii] / (T_TABLES * BAG_L);
    const int n_rows = in_sizes[c0] / T_TABLES;

    const int n_bags  = T_TABLES * B;            // 8192 warps
    const int threads = WARPS * 32;              // 64-thread blocks
    const int blocks  = (n_bags + WARPS - 1) / WARPS;   // 4096 blocks

    emb_bag_kernel<<<blocks, threads>>>(qw, candA, candB, indices, out,
                                        B, n_rows);
}